// round 5
// baseline (speedup 1.0000x reference)
#include <cuda_runtime.h>
#include <cstdint>

#define N_NODES 100000
#define N_EDGES 3200000

// Scratch accumulator [N_NODES, 16], initialized to x (folds the (1+eps)*x term).
__device__ __align__(16) float g_aggr[N_NODES * 16];

// 1 if edge_index is int64, 0 if int32. Written by probe_kernel each call.
__device__ int g_idx_is_64;

// ---------------------------------------------------------------------------
// Kernel 0: probe edge_index dtype.
// int32 data viewed as int64 has a nonzero hi word almost surely, so
// "all 64 probes in range" <=> genuinely int64.
// ---------------------------------------------------------------------------
__global__ void probe_kernel(const long long* __restrict__ ei) {
    if (threadIdx.x == 0 && blockIdx.x == 0) {
        int ok64 = 1;
        for (int i = 0; i < 64; i++) {
            long long v = ei[i];
            if (v < 0 || v >= N_NODES) { ok64 = 0; break; }
        }
        g_idx_is_64 = ok64;
    }
}

// ---------------------------------------------------------------------------
// Kernel 1: aggr = x
// ---------------------------------------------------------------------------
__global__ void init_aggr_kernel(const float4* __restrict__ x) {
    int i = blockIdx.x * blockDim.x + threadIdx.x;
    const int n4 = N_NODES * 16 / 4;
    if (i < n4) {
        reinterpret_cast<float4*>(g_aggr)[i] = x[i];
    }
}

// ---------------------------------------------------------------------------
// Kernel 2: per-edge message + reduction, 4 THREADS PER EDGE.
// Lane group l in {0..3} of an edge handles features [4l, 4l+4):
//   - loads one float4 of x[src]           (4 consecutive lanes -> same 128B line)
//   - computes 4 features of relu(x_j + lin1(ea))
//   - issues one red.global.add.v4.f32     (4 consecutive lanes -> 64B merged)
// ---------------------------------------------------------------------------
__device__ __forceinline__ void red_add_v4(float* gptr, float a, float b, float c, float d) {
    asm volatile("red.global.add.v4.f32 [%0], {%1, %2, %3, %4};"
                 :: "l"(gptr), "f"(a), "f"(b), "f"(c), "f"(d)
                 : "memory");
}

__global__ void __launch_bounds__(256) edge_kernel(
    const float* __restrict__ x,
    const void* __restrict__ edge_index,       // [2, E] int32 or int64
    const float* __restrict__ edge_attr,       // [E, 8]
    const float* __restrict__ lin1_w,          // [16, 8]
    const float* __restrict__ lin1_b)          // [16]
{
    __shared__ float sw[128];
    __shared__ float sb[16];
    if (threadIdx.x < 128) sw[threadIdx.x] = lin1_w[threadIdx.x];
    if (threadIdx.x < 16)  sb[threadIdx.x] = lin1_b[threadIdx.x];
    __syncthreads();

    int tid  = blockIdx.x * blockDim.x + threadIdx.x;
    int e    = tid >> 2;          // edge id
    int lane = tid & 3;           // feature group: features [4*lane, 4*lane+4)
    if (e >= N_EDGES) return;

    int src, dst;
    if (g_idx_is_64) {
        const long long* ei = (const long long*)edge_index;
        src = (int)ei[e];
        dst = (int)ei[(size_t)N_EDGES + e];
    } else {
        const int* ei = (const int*)edge_index;
        src = ei[e];
        dst = ei[N_EDGES + e];
    }
    if ((unsigned)src >= N_NODES || (unsigned)dst >= N_NODES) return;

    // edge_attr row (32B): all 4 lanes of the edge load the same two float4s;
    // warp covers 8 consecutive edges -> 256B contiguous, fully coalesced.
    const float4* ea = reinterpret_cast<const float4*>(edge_attr + (size_t)e * 8);
    float4 a0 = ea[0];
    float4 a1 = ea[1];

    // One float4 of x[src]: 4 lanes hit consecutive 16B of the same line.
    float4 xv = __ldg(reinterpret_cast<const float4*>(x + (size_t)src * 16) + lane);
    float xr[4] = {xv.x, xv.y, xv.z, xv.w};

    int k0 = lane * 4;
    float m[4];
#pragma unroll
    for (int j = 0; j < 4; j++) {
        const float* wk = sw + (k0 + j) * 8;
        float v = sb[k0 + j];
        v = fmaf(a0.x, wk[0], v);
        v = fmaf(a0.y, wk[1], v);
        v = fmaf(a0.z, wk[2], v);
        v = fmaf(a0.w, wk[3], v);
        v = fmaf(a1.x, wk[4], v);
        v = fmaf(a1.y, wk[5], v);
        v = fmaf(a1.z, wk[6], v);
        v = fmaf(a1.w, wk[7], v);
        v += xr[j];
        m[j] = fmaxf(v, 0.0f);
    }

    // 4 lanes -> 64B contiguous reduction at aggr[dst].
    red_add_v4(g_aggr + (size_t)dst * 16 + k0, m[0], m[1], m[2], m[3]);
}

// ---------------------------------------------------------------------------
// Kernel 3: out[n] = aggr[n] @ nn_w.T + nn_b   (16 -> 32), 8 THREADS PER NODE.
// Each thread computes 4 of the 32 outputs; warp stores 4 nodes x 128B
// perfectly coalesced.
// ---------------------------------------------------------------------------
__global__ void __launch_bounds__(256) node_kernel(
    const float* __restrict__ nn_w,   // [32, 16]
    const float* __restrict__ nn_b,   // [32]
    float* __restrict__ out)          // [N, 32]
{
    __shared__ float sw[512];
    __shared__ float sb[32];
    for (int i = threadIdx.x; i < 512; i += blockDim.x) sw[i] = nn_w[i];
    if (threadIdx.x < 32) sb[threadIdx.x] = nn_b[threadIdx.x];
    __syncthreads();

    int tid  = blockIdx.x * blockDim.x + threadIdx.x;
    int n    = tid >> 3;           // node id
    int lane = tid & 7;            // output group: outputs [4*lane, 4*lane+4)
    if (n >= N_NODES) return;

    const float4* ar = reinterpret_cast<const float4*>(g_aggr + (size_t)n * 16);
    float4 v0 = ar[0], v1 = ar[1], v2 = ar[2], v3 = ar[3];
    float in[16] = {v0.x, v0.y, v0.z, v0.w, v1.x, v1.y, v1.z, v1.w,
                    v2.x, v2.y, v2.z, v2.w, v3.x, v3.y, v3.z, v3.w};

    int j0 = lane * 4;
    float4 o;
    float* op = &o.x;
#pragma unroll
    for (int jj = 0; jj < 4; jj++) {
        const float* wj = sw + (j0 + jj) * 16;
        float acc = sb[j0 + jj];
#pragma unroll
        for (int k = 0; k < 16; k++) acc = fmaf(in[k], wj[k], acc);
        op[jj] = acc;
    }
    *reinterpret_cast<float4*>(out + (size_t)n * 32 + j0) = o;
}

// ---------------------------------------------------------------------------
extern "C" void kernel_launch(void* const* d_in, const int* in_sizes, int n_in,
                              void* d_out, int out_size) {
    const float* x          = (const float*)d_in[0];
    const void*  edge_index = d_in[1];
    const float* edge_attr  = (const float*)d_in[2];
    const float* lin1_w     = (const float*)d_in[3];
    const float* lin1_b     = (const float*)d_in[4];
    const float* nn_w       = (const float*)d_in[5];
    const float* nn_b       = (const float*)d_in[6];
    float*       out        = (float*)d_out;

    // 0) dtype probe
    probe_kernel<<<1, 32>>>((const long long*)edge_index);

    // 1) aggr = x
    {
        int n4 = N_NODES * 16 / 4;
        int threads = 256;
        int blocks = (n4 + threads - 1) / threads;
        init_aggr_kernel<<<blocks, threads>>>(reinterpret_cast<const float4*>(x));
    }
    // 2) edge messages + reductions (4 threads per edge)
    {
        long long total = (long long)N_EDGES * 4;
        int threads = 256;
        int blocks = (int)((total + threads - 1) / threads);
        edge_kernel<<<blocks, threads>>>(x, edge_index, edge_attr, lin1_w, lin1_b);
    }
    // 3) node update (8 threads per node)
    {
        long long total = (long long)N_NODES * 8;
        int threads = 256;
        int blocks = (int)((total + threads - 1) / threads);
        node_kernel<<<blocks, threads>>>(nn_w, nn_b, out);
    }
}

// round 6
// speedup vs baseline: 2.2162x; 2.2162x over previous
#include <cuda_runtime.h>
#include <cstdint>

#define N_NODES 100000
#define N_EDGES 3200000
#define EPB 256          // edges per block (3.2M / 256 = 12500 blocks, no tail)
#define ROW_PAD 20       // smem row stride in floats (80B: 16B-aligned, LDS conflict-free readback)

// Scratch accumulator [N_NODES, 16], initialized to x (folds the (1+eps)*x term).
__device__ __align__(16) float g_aggr[N_NODES * 16];

// 1 if edge_index is int64, 0 if int32. Written by probe_kernel each call.
__device__ int g_idx_is_64;

// ---------------------------------------------------------------------------
// Kernel 0: probe edge_index dtype.
// int32 data viewed as int64 has a nonzero hi word almost surely, so
// "all 64 probes in range" <=> genuinely int64.
// ---------------------------------------------------------------------------
__global__ void probe_kernel(const long long* __restrict__ ei) {
    if (threadIdx.x == 0 && blockIdx.x == 0) {
        int ok64 = 1;
        for (int i = 0; i < 64; i++) {
            long long v = ei[i];
            if (v < 0 || v >= N_NODES) { ok64 = 0; break; }
        }
        g_idx_is_64 = ok64;
    }
}

// ---------------------------------------------------------------------------
// Kernel 1: aggr = x
// ---------------------------------------------------------------------------
__global__ void init_aggr_kernel(const float4* __restrict__ x) {
    int i = blockIdx.x * blockDim.x + threadIdx.x;
    const int n4 = N_NODES * 16 / 4;
    if (i < n4) {
        reinterpret_cast<float4*>(g_aggr)[i] = x[i];
    }
}

// ---------------------------------------------------------------------------
// Kernel 2: edge messages + reductions, 1 thread/edge, smem-staged gather.
//   Phase 1: thread t loads src/dst/edge_attr of edge (block*256 + t);
//            src staged to smem.
//   Phase 2: cooperative gather: lane-quad q fetches the 4 float4 chunks of
//            x[src[row]] in ONE warp instruction (8 rows/warp-instr
//            -> ~1 L1tex wavefront per edge instead of 4).
//   Phase 3: thread t reads its full staged row (conflict-free via ROW_PAD),
//            computes relu(x_j + lin1(ea)), fires 4x red.global.add.v4.f32.
// ---------------------------------------------------------------------------
__device__ __forceinline__ void red_add_v4(float* gptr, float a, float b, float c, float d) {
    asm volatile("red.global.add.v4.f32 [%0], {%1, %2, %3, %4};"
                 :: "l"(gptr), "f"(a), "f"(b), "f"(c), "f"(d)
                 : "memory");
}

__global__ void __launch_bounds__(EPB) edge_kernel(
    const float* __restrict__ x,
    const void* __restrict__ edge_index,       // [2, E] int32 or int64
    const float* __restrict__ edge_attr,       // [E, 8]
    const float* __restrict__ lin1_w,          // [16, 8]
    const float* __restrict__ lin1_b)          // [16]
{
    __shared__ float sw[128];
    __shared__ float sb[16];
    __shared__ int   s_src[EPB];
    __shared__ __align__(16) float s_x[EPB * ROW_PAD];

    const int t = threadIdx.x;
    if (t < 128) sw[t] = lin1_w[t];
    if (t < 16)  sb[t] = lin1_b[t];

    const int e = blockIdx.x * EPB + t;   // grid sized exactly: always < N_EDGES

    int src, dst;
    if (g_idx_is_64) {
        const long long* ei = (const long long*)edge_index;
        src = (int)ei[e];
        dst = (int)ei[(size_t)N_EDGES + e];
    } else {
        const int* ei = (const int*)edge_index;
        src = ei[e];
        dst = ei[N_EDGES + e];
    }
    // Defensive: clamp src for the staged load; dst validated before RED.
    if ((unsigned)src >= N_NODES) src = 0;
    s_src[t] = src;

    // Edge attr row (32B), fully coalesced.
    const float4* ea = reinterpret_cast<const float4*>(edge_attr + (size_t)e * 8);
    float4 a0 = ea[0];
    float4 a1 = ea[1];

    __syncthreads();

    // Cooperative gather: lane-quads fetch row chunks.
    {
        const float4* x4 = reinterpret_cast<const float4*>(x);
        const int c     = t & 3;       // chunk within row
        const int rbase = t >> 2;      // row group
#pragma unroll
        for (int r = 0; r < 4; r++) {
            int row = r * 64 + rbase;
            int s   = s_src[row];                         // broadcast within quad
            float4 v = x4[(size_t)s * 4 + c];             // 8 rows per warp-instr
            *reinterpret_cast<float4*>(s_x + row * ROW_PAD + c * 4) = v;
        }
    }
    __syncthreads();

    // Read own staged row: 4x LDS.128 at stride 80B -> conflict-free phases.
    float4 v0 = *reinterpret_cast<const float4*>(s_x + t * ROW_PAD + 0);
    float4 v1 = *reinterpret_cast<const float4*>(s_x + t * ROW_PAD + 4);
    float4 v2 = *reinterpret_cast<const float4*>(s_x + t * ROW_PAD + 8);
    float4 v3 = *reinterpret_cast<const float4*>(s_x + t * ROW_PAD + 12);
    float xr[16] = {v0.x, v0.y, v0.z, v0.w, v1.x, v1.y, v1.z, v1.w,
                    v2.x, v2.y, v2.z, v2.w, v3.x, v3.y, v3.z, v3.w};

    float m[16];
#pragma unroll
    for (int k = 0; k < 16; k++) {
        const float* wk = sw + k * 8;   // uniform across warp -> broadcast LDS
        float v = sb[k];
        v = fmaf(a0.x, wk[0], v);
        v = fmaf(a0.y, wk[1], v);
        v = fmaf(a0.z, wk[2], v);
        v = fmaf(a0.w, wk[3], v);
        v = fmaf(a1.x, wk[4], v);
        v = fmaf(a1.y, wk[5], v);
        v = fmaf(a1.z, wk[6], v);
        v = fmaf(a1.w, wk[7], v);
        v += xr[k];
        m[k] = fmaxf(v, 0.0f);
    }

    if ((unsigned)dst >= N_NODES) return;
    float* ag = g_aggr + (size_t)dst * 16;
    red_add_v4(ag + 0,  m[0],  m[1],  m[2],  m[3]);
    red_add_v4(ag + 4,  m[4],  m[5],  m[6],  m[7]);
    red_add_v4(ag + 8,  m[8],  m[9],  m[10], m[11]);
    red_add_v4(ag + 12, m[12], m[13], m[14], m[15]);
}

// ---------------------------------------------------------------------------
// Kernel 3: out[n] = aggr[n] @ nn_w.T + nn_b   (16 -> 32), 2 THREADS PER NODE.
// Each thread computes 16 of the 32 outputs (one 64B half-row store group).
// ---------------------------------------------------------------------------
__global__ void __launch_bounds__(256) node_kernel(
    const float* __restrict__ nn_w,   // [32, 16]
    const float* __restrict__ nn_b,   // [32]
    float* __restrict__ out)          // [N, 32]
{
    __shared__ float sw[512];
    __shared__ float sb[32];
    for (int i = threadIdx.x; i < 512; i += blockDim.x) sw[i] = nn_w[i];
    if (threadIdx.x < 32) sb[threadIdx.x] = nn_b[threadIdx.x];
    __syncthreads();

    int tid  = blockIdx.x * blockDim.x + threadIdx.x;
    int n    = tid >> 1;            // node id
    int half = tid & 1;             // outputs [16*half, 16*half+16)
    if (n >= N_NODES) return;

    const float4* ar = reinterpret_cast<const float4*>(g_aggr + (size_t)n * 16);
    float4 u0 = ar[0], u1 = ar[1], u2 = ar[2], u3 = ar[3];
    float in[16] = {u0.x, u0.y, u0.z, u0.w, u1.x, u1.y, u1.z, u1.w,
                    u2.x, u2.y, u2.z, u2.w, u3.x, u3.y, u3.z, u3.w};

    int j0 = half * 16;
    float* orow = out + (size_t)n * 32 + j0;
#pragma unroll
    for (int j = 0; j < 16; j += 4) {
        float4 o;
        float* op = &o.x;
#pragma unroll
        for (int jj = 0; jj < 4; jj++) {
            const float* wj = sw + (j0 + j + jj) * 16;  // uniform -> broadcast
            float acc = sb[j0 + j + jj];
#pragma unroll
            for (int k = 0; k < 16; k++) acc = fmaf(in[k], wj[k], acc);
            op[jj] = acc;
        }
        *reinterpret_cast<float4*>(orow + j) = o;
    }
}

// ---------------------------------------------------------------------------
extern "C" void kernel_launch(void* const* d_in, const int* in_sizes, int n_in,
                              void* d_out, int out_size) {
    const float* x          = (const float*)d_in[0];
    const void*  edge_index = d_in[1];
    const float* edge_attr  = (const float*)d_in[2];
    const float* lin1_w     = (const float*)d_in[3];
    const float* lin1_b     = (const float*)d_in[4];
    const float* nn_w       = (const float*)d_in[5];
    const float* nn_b       = (const float*)d_in[6];
    float*       out        = (float*)d_out;

    // 0) dtype probe
    probe_kernel<<<1, 32>>>((const long long*)edge_index);

    // 1) aggr = x
    {
        int n4 = N_NODES * 16 / 4;
        int threads = 256;
        int blocks = (n4 + threads - 1) / threads;
        init_aggr_kernel<<<blocks, threads>>>(reinterpret_cast<const float4*>(x));
    }
    // 2) edge messages + reductions (1 thread/edge, staged gather)
    {
        int blocks = N_EDGES / EPB;   // 12500 exactly
        edge_kernel<<<blocks, EPB>>>(x, edge_index, edge_attr, lin1_w, lin1_b);
    }
    // 3) node update (2 threads per node)
    {
        long long total = (long long)N_NODES * 2;
        int threads = 256;
        int blocks = (int)((total + threads - 1) / threads);
        node_kernel<<<blocks, threads>>>(nn_w, nn_b, out);
    }
}

// round 7
// speedup vs baseline: 2.3591x; 1.0645x over previous
#include <cuda_runtime.h>
#include <cstdint>

#define N_NODES 100000
#define N_EDGES 3200000
#define EPB 256          // edges per block (3.2M / 256 = 12500 blocks, no tail)
#define ROW_PAD 20       // smem row stride in floats (80B: conflict-free LDS.128 readback)

// Scratch accumulator [N_NODES, 16], initialized to x (folds the (1+eps)*x term).
__device__ __align__(16) float g_aggr[N_NODES * 16];

// 1 if edge_index is int64, 0 if int32. Written by init kernel each call.
__device__ int g_idx_is_64;

// ---------------------------------------------------------------------------
// Packed f32x2 helpers (sm_103a FFMA2 path — ptxas never auto-fuses these).
// ---------------------------------------------------------------------------
__device__ __forceinline__ unsigned long long pack2(float lo, float hi) {
    unsigned long long d;
    asm("mov.b64 %0, {%1, %2};" : "=l"(d) : "f"(lo), "f"(hi));
    return d;
}
__device__ __forceinline__ void unpack2(unsigned long long d, float& lo, float& hi) {
    asm("mov.b64 {%0, %1}, %2;" : "=f"(lo), "=f"(hi) : "l"(d));
}
__device__ __forceinline__ unsigned long long fma2(unsigned long long a,
                                                   unsigned long long b,
                                                   unsigned long long c) {
    unsigned long long d;
    asm("fma.rn.f32x2 %0, %1, %2, %3;" : "=l"(d) : "l"(a), "l"(b), "l"(c));
    return d;
}
__device__ __forceinline__ unsigned long long add2(unsigned long long a,
                                                   unsigned long long b) {
    unsigned long long d;
    asm("add.rn.f32x2 %0, %1, %2;" : "=l"(d) : "l"(a), "l"(b));
    return d;
}

// ---------------------------------------------------------------------------
// Kernel 1: aggr = x ; block 0 thread 0 also probes edge_index dtype.
// int32 data viewed as int64 has a nonzero hi word almost surely, so
// "all 64 probes in range" <=> genuinely int64.
// ---------------------------------------------------------------------------
__global__ void init_aggr_kernel(const float4* __restrict__ x,
                                 const long long* __restrict__ ei) {
    int i = blockIdx.x * blockDim.x + threadIdx.x;
    if (i == 0) {
        int ok64 = 1;
        for (int p = 0; p < 64; p++) {
            long long v = ei[p];
            if (v < 0 || v >= N_NODES) { ok64 = 0; break; }
        }
        g_idx_is_64 = ok64;
    }
    const int n4 = N_NODES * 16 / 4;
    if (i < n4) {
        reinterpret_cast<float4*>(g_aggr)[i] = x[i];
    }
}

// ---------------------------------------------------------------------------
// Kernel 2: edge messages + reductions, 1 thread/edge, smem-staged gather,
// packed f32x2 compute (8 feature pairs).
// ---------------------------------------------------------------------------
__device__ __forceinline__ void red_add_v4(float* gptr, float a, float b, float c, float d) {
    asm volatile("red.global.add.v4.f32 [%0], {%1, %2, %3, %4};"
                 :: "l"(gptr), "f"(a), "f"(b), "f"(c), "f"(d)
                 : "memory");
}

__global__ void __launch_bounds__(EPB) edge_kernel(
    const float* __restrict__ x,
    const void* __restrict__ edge_index,       // [2, E] int32 or int64
    const float* __restrict__ edge_attr,       // [E, 8]
    const float* __restrict__ lin1_w,          // [16, 8]
    const float* __restrict__ lin1_b)          // [16]
{
    // Weights pre-paired: sw2[(p*8+j)*2 + h] = w[2p+h][j]  (pair p covers
    // features 2p, 2p+1). 8B-aligned pairs load directly as FFMA2 operands.
    __shared__ __align__(16) float sw2[256];
    __shared__ __align__(8)  float sb[16];
    __shared__ int s_src[EPB];
    __shared__ __align__(16) float s_x[EPB * ROW_PAD];

    const int t = threadIdx.x;
    if (t < 128) {
        int k = t >> 3, j = t & 7;
        sw2[(((k >> 1) * 8 + j) << 1) + (k & 1)] = lin1_w[t];
    }
    if (t < 16) sb[t] = lin1_b[t];

    const int e = blockIdx.x * EPB + t;   // grid sized exactly: always < N_EDGES

    int src, dst;
    if (g_idx_is_64) {
        const long long* ei = (const long long*)edge_index;
        src = (int)ei[e];
        dst = (int)ei[(size_t)N_EDGES + e];
    } else {
        const int* ei = (const int*)edge_index;
        src = ei[e];
        dst = ei[N_EDGES + e];
    }
    if ((unsigned)src >= N_NODES) src = 0;   // defensive; dst checked pre-RED
    s_src[t] = src;

    // Edge attr row (32B), fully coalesced; replicate each feature into a pair.
    const float4* ea = reinterpret_cast<const float4*>(edge_attr + (size_t)e * 8);
    float4 a0 = ea[0];
    float4 a1 = ea[1];
    unsigned long long ap[8];
    ap[0] = pack2(a0.x, a0.x); ap[1] = pack2(a0.y, a0.y);
    ap[2] = pack2(a0.z, a0.z); ap[3] = pack2(a0.w, a0.w);
    ap[4] = pack2(a1.x, a1.x); ap[5] = pack2(a1.y, a1.y);
    ap[6] = pack2(a1.z, a1.z); ap[7] = pack2(a1.w, a1.w);

    __syncthreads();

    // Cooperative gather: lane-quads fetch row chunks (8 rows / warp-instr).
    {
        const float4* x4 = reinterpret_cast<const float4*>(x);
        const int c     = t & 3;
        const int rbase = t >> 2;
#pragma unroll
        for (int r = 0; r < 4; r++) {
            int row = r * 64 + rbase;
            int s   = s_src[row];
            float4 v = x4[(size_t)s * 4 + c];
            *reinterpret_cast<float4*>(s_x + row * ROW_PAD + c * 4) = v;
        }
    }
    __syncthreads();

    // Own staged row: 4x LDS.128, conflict-free (stride 80B).
    float4 v0 = *reinterpret_cast<const float4*>(s_x + t * ROW_PAD + 0);
    float4 v1 = *reinterpret_cast<const float4*>(s_x + t * ROW_PAD + 4);
    float4 v2 = *reinterpret_cast<const float4*>(s_x + t * ROW_PAD + 8);
    float4 v3 = *reinterpret_cast<const float4*>(s_x + t * ROW_PAD + 12);
    unsigned long long xp[8];
    xp[0] = pack2(v0.x, v0.y); xp[1] = pack2(v0.z, v0.w);
    xp[2] = pack2(v1.x, v1.y); xp[3] = pack2(v1.z, v1.w);
    xp[4] = pack2(v2.x, v2.y); xp[5] = pack2(v2.z, v2.w);
    xp[6] = pack2(v3.x, v3.y); xp[7] = pack2(v3.z, v3.w);

    float m[16];
#pragma unroll
    for (int p = 0; p < 8; p++) {
        unsigned long long acc =
            *reinterpret_cast<const unsigned long long*>(sb + 2 * p);   // bias pair
        const unsigned long long* wp =
            reinterpret_cast<const unsigned long long*>(sw2) + p * 8;
#pragma unroll
        for (int j = 0; j < 8; j += 2) {
            ulonglong2 ww = *reinterpret_cast<const ulonglong2*>(wp + j);  // LDS.128
            acc = fma2(ap[j],     ww.x, acc);
            acc = fma2(ap[j + 1], ww.y, acc);
        }
        acc = add2(acc, xp[p]);
        float lo, hi;
        unpack2(acc, lo, hi);
        m[2 * p]     = fmaxf(lo, 0.0f);
        m[2 * p + 1] = fmaxf(hi, 0.0f);
    }

    if ((unsigned)dst >= N_NODES) return;
    float* ag = g_aggr + (size_t)dst * 16;
    red_add_v4(ag + 0,  m[0],  m[1],  m[2],  m[3]);
    red_add_v4(ag + 4,  m[4],  m[5],  m[6],  m[7]);
    red_add_v4(ag + 8,  m[8],  m[9],  m[10], m[11]);
    red_add_v4(ag + 12, m[12], m[13], m[14], m[15]);
}

// ---------------------------------------------------------------------------
// Kernel 3: out[n] = aggr[n] @ nn_w.T + nn_b   (16 -> 32), 1 THREAD PER NODE,
// packed f32x2 compute (16 output pairs).
// ---------------------------------------------------------------------------
__global__ void __launch_bounds__(256) node_kernel(
    const float* __restrict__ nn_w,   // [32, 16]
    const float* __restrict__ nn_b,   // [32]
    float* __restrict__ out)          // [N, 32]
{
    // sw2[(jp*16+k)*2 + h] = nn_w[(2jp+h)*16 + k]  (pair jp = outputs 2jp, 2jp+1)
    __shared__ __align__(16) float sw2[1024];
    __shared__ __align__(8)  float sb[32];
    for (int i = threadIdx.x; i < 512; i += blockDim.x) {
        int row = i >> 4, k = i & 15;
        sw2[((((row >> 1) << 4) + k) << 1) + (row & 1)] = nn_w[i];
    }
    if (threadIdx.x < 32) sb[threadIdx.x] = nn_b[threadIdx.x];
    __syncthreads();

    int n = blockIdx.x * blockDim.x + threadIdx.x;
    if (n >= N_NODES) return;

    const float4* ar = reinterpret_cast<const float4*>(g_aggr + (size_t)n * 16);
    float4 u0 = ar[0], u1 = ar[1], u2 = ar[2], u3 = ar[3];
    float in[16] = {u0.x, u0.y, u0.z, u0.w, u1.x, u1.y, u1.z, u1.w,
                    u2.x, u2.y, u2.z, u2.w, u3.x, u3.y, u3.z, u3.w};
    unsigned long long inp[16];
#pragma unroll
    for (int k = 0; k < 16; k++) inp[k] = pack2(in[k], in[k]);

    float* orow = out + (size_t)n * 32;
#pragma unroll
    for (int jp4 = 0; jp4 < 16; jp4 += 2) {       // two pairs -> one float4 store
        float4 o;
#pragma unroll
        for (int q = 0; q < 2; q++) {
            int jp = jp4 + q;
            unsigned long long acc =
                *reinterpret_cast<const unsigned long long*>(sb + 2 * jp);
            const unsigned long long* wp =
                reinterpret_cast<const unsigned long long*>(sw2) + jp * 16;
#pragma unroll
            for (int k = 0; k < 16; k += 2) {
                ulonglong2 ww = *reinterpret_cast<const ulonglong2*>(wp + k);
                acc = fma2(inp[k],     ww.x, acc);
                acc = fma2(inp[k + 1], ww.y, acc);
            }
            float lo, hi;
            unpack2(acc, lo, hi);
            if (q == 0) { o.x = lo; o.y = hi; }
            else        { o.z = lo; o.w = hi; }
        }
        *reinterpret_cast<float4*>(orow + jp4 * 2) = o;
    }
}

// ---------------------------------------------------------------------------
extern "C" void kernel_launch(void* const* d_in, const int* in_sizes, int n_in,
                              void* d_out, int out_size) {
    const float* x          = (const float*)d_in[0];
    const void*  edge_index = d_in[1];
    const float* edge_attr  = (const float*)d_in[2];
    const float* lin1_w     = (const float*)d_in[3];
    const float* lin1_b     = (const float*)d_in[4];
    const float* nn_w       = (const float*)d_in[5];
    const float* nn_b       = (const float*)d_in[6];
    float*       out        = (float*)d_out;

    // 1) aggr = x (+ dtype probe on thread 0)
    {
        int n4 = N_NODES * 16 / 4;
        int threads = 256;
        int blocks = (n4 + threads - 1) / threads;
        init_aggr_kernel<<<blocks, threads>>>(
            reinterpret_cast<const float4*>(x), (const long long*)edge_index);
    }
    // 2) edge messages + reductions
    {
        int blocks = N_EDGES / EPB;   // 12500 exactly
        edge_kernel<<<blocks, EPB>>>(x, edge_index, edge_attr, lin1_w, lin1_b);
    }
    // 3) node update (1 thread per node)
    {
        int threads = 256;
        int blocks = (N_NODES + threads - 1) / threads;
        node_kernel<<<blocks, threads>>>(nn_w, nn_b, out);
    }
}

// round 8
// speedup vs baseline: 2.4394x; 1.0340x over previous
#include <cuda_runtime.h>
#include <cstdint>

#define N_NODES 100000
#define N_EDGES 3200000
#define EPB 256          // edges per block (3.2M / 256 = 12500 blocks, no tail)
#define EA_PAD 20        // s_ea row stride in floats (80B: conflict-free quad readback)

// Scratch accumulator [N_NODES, 16], initialized to x (folds the (1+eps)*x term).
__device__ __align__(16) float g_aggr[N_NODES * 16];

// 1 if edge_index is int64, 0 if int32. Written by init kernel each call.
__device__ int g_idx_is_64;

// ---------------------------------------------------------------------------
// Packed f32x2 helpers (sm_103a FFMA2 path — ptxas never auto-fuses these).
// ---------------------------------------------------------------------------
__device__ __forceinline__ unsigned long long pack2(float lo, float hi) {
    unsigned long long d;
    asm("mov.b64 %0, {%1, %2};" : "=l"(d) : "f"(lo), "f"(hi));
    return d;
}
__device__ __forceinline__ void unpack2(unsigned long long d, float& lo, float& hi) {
    asm("mov.b64 {%0, %1}, %2;" : "=f"(lo), "=f"(hi) : "l"(d));
}
__device__ __forceinline__ unsigned long long fma2(unsigned long long a,
                                                   unsigned long long b,
                                                   unsigned long long c) {
    unsigned long long d;
    asm("fma.rn.f32x2 %0, %1, %2, %3;" : "=l"(d) : "l"(a), "l"(b), "l"(c));
    return d;
}
__device__ __forceinline__ unsigned long long add2(unsigned long long a,
                                                   unsigned long long b) {
    unsigned long long d;
    asm("add.rn.f32x2 %0, %1, %2;" : "=l"(d) : "l"(a), "l"(b));
    return d;
}

// ---------------------------------------------------------------------------
// Kernel 1: aggr = x ; block 0 thread 0 also probes edge_index dtype.
// ---------------------------------------------------------------------------
__global__ void init_aggr_kernel(const float4* __restrict__ x,
                                 const long long* __restrict__ ei) {
    int i = blockIdx.x * blockDim.x + threadIdx.x;
    if (i == 0) {
        int ok64 = 1;
        for (int p = 0; p < 64; p++) {
            long long v = ei[p];
            if (v < 0 || v >= N_NODES) { ok64 = 0; break; }
        }
        g_idx_is_64 = ok64;
    }
    const int n4 = N_NODES * 16 / 4;
    if (i < n4) {
        reinterpret_cast<float4*>(g_aggr)[i] = x[i];
    }
}

// ---------------------------------------------------------------------------
// Kernel 2: edge messages + reductions.
// Block = 256 edges. Thread t owns chunk c = t&3 (features 4c..4c+3) of the
// 8 edges e = (t>>2) + 64r, r=0..3.
//   - edge_attr / src / dst staged to smem once (coalesced 1x traffic)
//   - x gather: quad lanes read consecutive 16B chunks of x[src]
//     -> 8 distinct 128B lines per warp-instruction (1 wf/edge)
//   - RED: quad lanes cover contiguous 64B of aggr[dst]
//     -> 8 distinct lines per warp-instruction (1 wf/edge, was 4)
// edge_attr staged DUPLICATED (a0,a0,a1,a1,...) so readback LDS.128 yields
// ready-made f32x2 operands with no mov.b64 packing.
// ---------------------------------------------------------------------------
__device__ __forceinline__ void red_add_v4(float* gptr, float a, float b, float c, float d) {
    asm volatile("red.global.add.v4.f32 [%0], {%1, %2, %3, %4};"
                 :: "l"(gptr), "f"(a), "f"(b), "f"(c), "f"(d)
                 : "memory");
}

__global__ void __launch_bounds__(EPB) edge_kernel(
    const float* __restrict__ x,
    const void* __restrict__ edge_index,       // [2, E] int32 or int64
    const float* __restrict__ edge_attr,       // [E, 8]
    const float* __restrict__ lin1_w,          // [16, 8]
    const float* __restrict__ lin1_b)          // [16]
{
    // Pair-interleaved weights: sw2 u64 slot [p*8+j] = (w[2p][j], w[2p+1][j]).
    __shared__ __align__(16) float sw2[256];
    __shared__ __align__(16) float sb[16];
    __shared__ int s_src[EPB];
    __shared__ int s_dst[EPB];
    __shared__ __align__(16) float s_ea[EPB * EA_PAD];   // duplicated attrs

    const int t = threadIdx.x;
    const int c = t & 3;        // feature chunk
    const int qi = t >> 2;      // edge-group index (0..63)

    if (t < 128) {
        int k = t >> 3, j = t & 7;
        sw2[(((k >> 1) * 8 + j) << 1) + (k & 1)] = lin1_w[t];
    }
    if (t < 16) sb[t] = lin1_b[t];

    // ---- Stage edges: thread t handles edge base + t ----
    const int e = blockIdx.x * EPB + t;   // exact grid: always < N_EDGES
    int src, dst;
    if (g_idx_is_64) {
        const long long* ei = (const long long*)edge_index;
        src = (int)ei[e];
        dst = (int)ei[(size_t)N_EDGES + e];
    } else {
        const int* ei = (const int*)edge_index;
        src = ei[e];
        dst = ei[N_EDGES + e];
    }
    if ((unsigned)src >= N_NODES) src = 0;   // defensive; dst checked pre-RED
    s_src[t] = src;
    s_dst[t] = dst;

    const float4* ea = reinterpret_cast<const float4*>(edge_attr + (size_t)e * 8);
    float4 a0 = ea[0];
    float4 a1 = ea[1];
    float* eab = s_ea + t * EA_PAD;
    *reinterpret_cast<float4*>(eab + 0)  = make_float4(a0.x, a0.x, a0.y, a0.y);
    *reinterpret_cast<float4*>(eab + 4)  = make_float4(a0.z, a0.z, a0.w, a0.w);
    *reinterpret_cast<float4*>(eab + 8)  = make_float4(a1.x, a1.x, a1.y, a1.y);
    *reinterpret_cast<float4*>(eab + 12) = make_float4(a1.z, a1.z, a1.w, a1.w);

    __syncthreads();

    // ---- Hoist this thread's weight pairs (p = 2c, 2c+1) into registers ----
    const ulonglong2* sw2v = reinterpret_cast<const ulonglong2*>(sw2);
    ulonglong2 w0[4], w1[4];    // w0[j2] = pairs for p=2c, j=2*j2, 2*j2+1
#pragma unroll
    for (int j2 = 0; j2 < 4; j2++) {
        w0[j2] = sw2v[(2 * c) * 4 + j2];
        w1[j2] = sw2v[(2 * c + 1) * 4 + j2];
    }
    const unsigned long long bias0 =
        reinterpret_cast<const unsigned long long*>(sb)[2 * c];
    const unsigned long long bias1 =
        reinterpret_cast<const unsigned long long*>(sb)[2 * c + 1];

    const float4* x4 = reinterpret_cast<const float4*>(x);

    // ---- Process 8 edges: chunk c of edge qi + 64r ----
#pragma unroll
    for (int r = 0; r < 4; r++) {
        const int el = qi + 64 * r;
        const int ssrc = s_src[el];
        const int sdst = s_dst[el];

        // quad lanes c=0..3 -> consecutive 16B of x[ssrc] (1 line per edge)
        float4 xv = __ldg(x4 + (size_t)ssrc * 4 + c);

        // duplicated attrs: 4x LDS.128 = 8 packed pairs, quad-broadcast,
        // 8 distinct rows per warp at stride 80B -> conflict-free
        const ulonglong2* ear =
            reinterpret_cast<const ulonglong2*>(s_ea + el * EA_PAD);
        ulonglong2 e0 = ear[0];   // (a0,a0),(a1,a1)
        ulonglong2 e1 = ear[1];   // (a2,a2),(a3,a3)
        ulonglong2 e2 = ear[2];
        ulonglong2 e3 = ear[3];

        unsigned long long acc0 = bias0, acc1 = bias1;
        acc0 = fma2(e0.x, w0[0].x, acc0);  acc1 = fma2(e0.x, w1[0].x, acc1);
        acc0 = fma2(e0.y, w0[0].y, acc0);  acc1 = fma2(e0.y, w1[0].y, acc1);
        acc0 = fma2(e1.x, w0[1].x, acc0);  acc1 = fma2(e1.x, w1[1].x, acc1);
        acc0 = fma2(e1.y, w0[1].y, acc0);  acc1 = fma2(e1.y, w1[1].y, acc1);
        acc0 = fma2(e2.x, w0[2].x, acc0);  acc1 = fma2(e2.x, w1[2].x, acc1);
        acc0 = fma2(e2.y, w0[2].y, acc0);  acc1 = fma2(e2.y, w1[2].y, acc1);
        acc0 = fma2(e3.x, w0[3].x, acc0);  acc1 = fma2(e3.x, w1[3].x, acc1);
        acc0 = fma2(e3.y, w0[3].y, acc0);  acc1 = fma2(e3.y, w1[3].y, acc1);

        acc0 = add2(acc0, pack2(xv.x, xv.y));
        acc1 = add2(acc1, pack2(xv.z, xv.w));

        float m0, m1, m2, m3;
        unpack2(acc0, m0, m1);
        unpack2(acc1, m2, m3);
        m0 = fmaxf(m0, 0.0f); m1 = fmaxf(m1, 0.0f);
        m2 = fmaxf(m2, 0.0f); m3 = fmaxf(m3, 0.0f);

        // quad lanes -> contiguous 64B reduction at aggr[sdst] (1 line/edge)
        if ((unsigned)sdst < N_NODES) {
            red_add_v4(g_aggr + (size_t)sdst * 16 + c * 4, m0, m1, m2, m3);
        }
    }
}

// ---------------------------------------------------------------------------
// Kernel 3: out[n] = aggr[n] @ nn_w.T + nn_b   (16 -> 32), 1 thread/node,
// packed f32x2 compute (16 output pairs). (Unchanged from R6.)
// ---------------------------------------------------------------------------
__global__ void __launch_bounds__(256) node_kernel(
    const float* __restrict__ nn_w,   // [32, 16]
    const float* __restrict__ nn_b,   // [32]
    float* __restrict__ out)          // [N, 32]
{
    __shared__ __align__(16) float sw2[1024];
    __shared__ __align__(8)  float sb[32];
    for (int i = threadIdx.x; i < 512; i += blockDim.x) {
        int row = i >> 4, k = i & 15;
        sw2[((((row >> 1) << 4) + k) << 1) + (row & 1)] = nn_w[i];
    }
    if (threadIdx.x < 32) sb[threadIdx.x] = nn_b[threadIdx.x];
    __syncthreads();

    int n = blockIdx.x * blockDim.x + threadIdx.x;
    if (n >= N_NODES) return;

    const float4* ar = reinterpret_cast<const float4*>(g_aggr + (size_t)n * 16);
    float4 u0 = ar[0], u1 = ar[1], u2 = ar[2], u3 = ar[3];
    float in[16] = {u0.x, u0.y, u0.z, u0.w, u1.x, u1.y, u1.z, u1.w,
                    u2.x, u2.y, u2.z, u2.w, u3.x, u3.y, u3.z, u3.w};
    unsigned long long inp[16];
#pragma unroll
    for (int k = 0; k < 16; k++) inp[k] = pack2(in[k], in[k]);

    float* orow = out + (size_t)n * 32;
#pragma unroll
    for (int jp4 = 0; jp4 < 16; jp4 += 2) {
        float4 o;
#pragma unroll
        for (int q = 0; q < 2; q++) {
            int jp = jp4 + q;
            unsigned long long acc =
                *reinterpret_cast<const unsigned long long*>(sb + 2 * jp);
            const unsigned long long* wp =
                reinterpret_cast<const unsigned long long*>(sw2) + jp * 16;
#pragma unroll
            for (int k = 0; k < 16; k += 2) {
                ulonglong2 ww = *reinterpret_cast<const ulonglong2*>(wp + k);
                acc = fma2(inp[k],     ww.x, acc);
                acc = fma2(inp[k + 1], ww.y, acc);
            }
            float lo, hi;
            unpack2(acc, lo, hi);
            if (q == 0) { o.x = lo; o.y = hi; }
            else        { o.z = lo; o.w = hi; }
        }
        *reinterpret_cast<float4*>(orow + jp4 * 2) = o;
    }
}

// ---------------------------------------------------------------------------
extern "C" void kernel_launch(void* const* d_in, const int* in_sizes, int n_in,
                              void* d_out, int out_size) {
    const float* x          = (const float*)d_in[0];
    const void*  edge_index = d_in[1];
    const float* edge_attr  = (const float*)d_in[2];
    const float* lin1_w     = (const float*)d_in[3];
    const float* lin1_b     = (const float*)d_in[4];
    const float* nn_w       = (const float*)d_in[5];
    const float* nn_b       = (const float*)d_in[6];
    float*       out        = (float*)d_out;

    // 1) aggr = x (+ dtype probe on thread 0)
    {
        int n4 = N_NODES * 16 / 4;
        int threads = 256;
        int blocks = (n4 + threads - 1) / threads;
        init_aggr_kernel<<<blocks, threads>>>(
            reinterpret_cast<const float4*>(x), (const long long*)edge_index);
    }
    // 2) edge messages + reductions
    {
        int blocks = N_EDGES / EPB;   // 12500 exactly
        edge_kernel<<<blocks, EPB>>>(x, edge_index, edge_attr, lin1_w, lin1_b);
    }
    // 3) node update
    {
        int threads = 256;
        int blocks = (N_NODES + threads - 1) / threads;
        node_kernel<<<blocks, threads>>>(nn_w, nn_b, out);
    }
}